// round 15
// baseline (speedup 1.0000x reference)
#include <cuda_runtime.h>
#include <cuda_fp16.h>
#include <mma.h>
#include <math.h>

using namespace nvcuda;

#define NMAX 100000
#define EMAX 3200000
#define D 128

// ---------------- scratch (device globals: allocation-guard-safe) ----------
__device__ int   g_deg[NMAX];
__device__ int   g_cursor[NMAX];
__device__ int   g_rowstart[NMAX + 1];
__device__ int   g_part[1024];
__device__ float g_norm[NMAX];    // deg^-1/2
__device__ float g_norm2[NMAX];   // deg^-1
__device__ __align__(16) int g_csr_src[EMAX];
// fp16 feature rows: 128 halfs = 256 B = 16 uint4 per row
__device__ __align__(16) uint4 g_hX[(size_t)NMAX * 16];
__device__ __align__(16) uint4 g_hA[(size_t)NMAX * 16];
__device__ __align__(16) uint4 g_hB[(size_t)NMAX * 16];
__device__ __align__(16) __half g_W1h[D * D];
__device__ __align__(16) __half g_W2h[D * D];
__device__ float g_accum[D];

// ---------------- init: zero degree counters + mean accumulator ------------
__global__ void k_init(int n) {
    int i = blockIdx.x * blockDim.x + threadIdx.x;
    if (i < n) g_deg[i] = 0;
    if (i < D) g_accum[i] = 0.f;
}

// ---------------- degree count (int4 vectorized) ---------------------------
__global__ void k_deg(const int4* __restrict__ dst4, int e4) {
    int i = blockIdx.x * blockDim.x + threadIdx.x;
    if (i < e4) {
        int4 d = dst4[i];
        atomicAdd(&g_deg[d.x], 1);
        atomicAdd(&g_deg[d.y], 1);
        atomicAdd(&g_deg[d.z], 1);
        atomicAdd(&g_deg[d.w], 1);
    }
}
__global__ void k_deg_tail(const int* __restrict__ dst, int beg, int e_cnt) {
    int i = beg + blockIdx.x * blockDim.x + threadIdx.x;
    if (i < e_cnt) atomicAdd(&g_deg[dst[i]], 1);
}

// ---------------- scan phase 1 ---------------------------------------------
__global__ void k_scan1(int n) {
    __shared__ int s[1024];
    int t = threadIdx.x;
    int i = blockIdx.x * 1024 + t;
    int v = (i < n) ? g_deg[i] : 0;
    s[t] = v;
    __syncthreads();
    for (int off = 1; off < 1024; off <<= 1) {
        int tmp = (t >= off) ? s[t - off] : 0;
        __syncthreads();
        s[t] += tmp;
        __syncthreads();
    }
    if (i < n) g_rowstart[i] = s[t] - v;
    if (t == 1023) g_part[blockIdx.x] = s[t];
}

// ---------------- scan phase 2 ---------------------------------------------
__global__ void k_scan2(int nb) {
    __shared__ int s[1024];
    int t = threadIdx.x;
    int v = (t < nb) ? g_part[t] : 0;
    s[t] = v;
    __syncthreads();
    for (int off = 1; off < 1024; off <<= 1) {
        int tmp = (t >= off) ? s[t - off] : 0;
        __syncthreads();
        s[t] += tmp;
        __syncthreads();
    }
    if (t < nb) g_part[t] = s[t] - v;
}

// ---------------- scan phase 3 ---------------------------------------------
__global__ void k_scan3(int n, int e_cnt) {
    int i = blockIdx.x * blockDim.x + threadIdx.x;
    if (i < n) {
        int r = g_rowstart[i] + g_part[i >> 10];
        g_rowstart[i] = r;
        g_cursor[i]   = r;
        float d = (float)g_deg[i];
        if (d < 1.f) d = 1.f;
        float nr = rsqrtf(d);
        g_norm[i]  = nr;
        g_norm2[i] = nr * nr;
    }
    if (i == 0) g_rowstart[n] = e_cnt;
}

// ---------------- CSR fill (int4 vectorized) -------------------------------
__global__ void k_fill(const int4* __restrict__ src4, const int4* __restrict__ dst4, int e4) {
    int i = blockIdx.x * blockDim.x + threadIdx.x;
    if (i < e4) {
        int4 s = src4[i];
        int4 d = dst4[i];
        int p;
        p = atomicAdd(&g_cursor[d.x], 1); g_csr_src[p] = s.x;
        p = atomicAdd(&g_cursor[d.y], 1); g_csr_src[p] = s.y;
        p = atomicAdd(&g_cursor[d.z], 1); g_csr_src[p] = s.z;
        p = atomicAdd(&g_cursor[d.w], 1); g_csr_src[p] = s.w;
    }
}
__global__ void k_fill_tail(const int* __restrict__ src, const int* __restrict__ dst,
                            int beg, int e_cnt) {
    int i = beg + blockIdx.x * blockDim.x + threadIdx.x;
    if (i < e_cnt) {
        int d = dst[i];
        int pos = atomicAdd(&g_cursor[d], 1);
        g_csr_src[pos] = src[i];
    }
}

// ---------------- weight fp32 -> fp16 --------------------------------------
__global__ void k_cvtW(const float4* __restrict__ W, uint2* __restrict__ Wh, int total4) {
    int i = blockIdx.x * blockDim.x + threadIdx.x;
    if (i < total4) {
        float4 v = W[i];
        __half2 a = __floats2half2_rn(v.x, v.y);
        __half2 b = __floats2half2_rn(v.z, v.w);
        uint2 o;
        o.x = *(unsigned*)&a;
        o.y = *(unsigned*)&b;
        Wh[i] = o;
    }
}

// ---------------- prescale: xs = fp16(norm[row] * x) -----------------------
__global__ void k_prescale(const float4* __restrict__ x, uint2* __restrict__ xs, int total4) {
    int i = blockIdx.x * blockDim.x + threadIdx.x;
    if (i < total4) {
        float nr = g_norm[i >> 5];
        float4 v = x[i];
        __half2 a = __floats2half2_rn(nr * v.x, nr * v.y);
        __half2 b = __floats2half2_rn(nr * v.z, nr * v.w);
        uint2 o;
        o.x = *(unsigned*)&a;
        o.y = *(unsigned*)&b;
        xs[i] = o;
    }
}

// ---------------- pure-add fp16 propagation, paired-edge uint4 -------------
// One warp per dst node. Lanes [0,16) read edge e's source row, lanes [16,32)
// read edge e+1's source row (SAME dst node -> no divergence). Each lane holds
// 16 B (4 half2) of the 256 B row. Final cross-half combine via shfl_xor(16).
// 8-edge unroll: 4 row LDG + 4 idx LDG per 8 edges = 1.0 LDG/edge.
__global__ void k_prop_add(const uint4* __restrict__ hin, uint4* __restrict__ hout,
                           const float* __restrict__ scl, int n) {
    int w    = (int)((blockIdx.x * (unsigned)blockDim.x + threadIdx.x) >> 5);
    int lane = threadIdx.x & 31;
    if (w >= n) return;
    int e    = g_rowstart[w];
    int end  = g_rowstart[w + 1];
    int half = lane >> 4;     // 0 or 1
    int l    = lane & 15;     // uint4 index within row

    __half2 z = __float2half2_rn(0.f);
    __half2 a0 = z, a1 = z, a2 = z, a3 = z;   // acc set A
    __half2 b0 = z, b1 = z, b2 = z, b3 = z;   // acc set B

    for (; e + 8 <= end; e += 8) {
        int s0 = g_csr_src[e     + half];
        int s1 = g_csr_src[e + 2 + half];
        int s2 = g_csr_src[e + 4 + half];
        int s3 = g_csr_src[e + 6 + half];
        uint4 r0 = __ldg(&hin[(size_t)s0 * 16 + l]);
        uint4 r1 = __ldg(&hin[(size_t)s1 * 16 + l]);
        uint4 r2 = __ldg(&hin[(size_t)s2 * 16 + l]);
        uint4 r3 = __ldg(&hin[(size_t)s3 * 16 + l]);
        a0 = __hadd2(a0, *(__half2*)&r0.x); a1 = __hadd2(a1, *(__half2*)&r0.y);
        a2 = __hadd2(a2, *(__half2*)&r0.z); a3 = __hadd2(a3, *(__half2*)&r0.w);
        b0 = __hadd2(b0, *(__half2*)&r1.x); b1 = __hadd2(b1, *(__half2*)&r1.y);
        b2 = __hadd2(b2, *(__half2*)&r1.z); b3 = __hadd2(b3, *(__half2*)&r1.w);
        a0 = __hadd2(a0, *(__half2*)&r2.x); a1 = __hadd2(a1, *(__half2*)&r2.y);
        a2 = __hadd2(a2, *(__half2*)&r2.z); a3 = __hadd2(a3, *(__half2*)&r2.w);
        b0 = __hadd2(b0, *(__half2*)&r3.x); b1 = __hadd2(b1, *(__half2*)&r3.y);
        b2 = __hadd2(b2, *(__half2*)&r3.z); b3 = __hadd2(b3, *(__half2*)&r3.w);
    }
    for (; e + 2 <= end; e += 2) {
        int s0 = g_csr_src[e + half];
        uint4 r0 = __ldg(&hin[(size_t)s0 * 16 + l]);
        a0 = __hadd2(a0, *(__half2*)&r0.x); a1 = __hadd2(a1, *(__half2*)&r0.y);
        a2 = __hadd2(a2, *(__half2*)&r0.z); a3 = __hadd2(a3, *(__half2*)&r0.w);
    }
    if (e < end && half == 0) {   // last odd edge: half 0 only
        int s0 = g_csr_src[e];
        uint4 r0 = __ldg(&hin[(size_t)s0 * 16 + l]);
        a0 = __hadd2(a0, *(__half2*)&r0.x); a1 = __hadd2(a1, *(__half2*)&r0.y);
        a2 = __hadd2(a2, *(__half2*)&r0.z); a3 = __hadd2(a3, *(__half2*)&r0.w);
    }

    // merge acc sets, then combine across half-warps (lane l <-> lane l+16)
    a0 = __hadd2(a0, b0); a1 = __hadd2(a1, b1);
    a2 = __hadd2(a2, b2); a3 = __hadd2(a3, b3);
    unsigned u;
    u = __shfl_xor_sync(0xffffffffu, *(unsigned*)&a0, 16); a0 = __hadd2(a0, *(__half2*)&u);
    u = __shfl_xor_sync(0xffffffffu, *(unsigned*)&a1, 16); a1 = __hadd2(a1, *(__half2*)&u);
    u = __shfl_xor_sync(0xffffffffu, *(unsigned*)&a2, 16); a2 = __hadd2(a2, *(__half2*)&u);
    u = __shfl_xor_sync(0xffffffffu, *(unsigned*)&a3, 16); a3 = __hadd2(a3, *(__half2*)&u);

    if (half == 0) {
        float f = scl[w];
        float2 f0 = __half22float2(a0);
        float2 f1 = __half22float2(a1);
        float2 f2 = __half22float2(a2);
        float2 f3 = __half22float2(a3);
        __half2 o0 = __floats2half2_rn(f * f0.x, f * f0.y);
        __half2 o1 = __floats2half2_rn(f * f1.x, f * f1.y);
        __half2 o2 = __floats2half2_rn(f * f2.x, f * f2.y);
        __half2 o3 = __floats2half2_rn(f * f3.x, f * f3.y);
        uint4 o;
        o.x = *(unsigned*)&o0;
        o.y = *(unsigned*)&o1;
        o.z = *(unsigned*)&o2;
        o.w = *(unsigned*)&o3;
        hout[(size_t)w * 16 + l] = o;
    }
}

// ---------------- tensor-core GEMM + bias + relu (R10-proven core) ---------
// C[n,128] = relu(h[n,128] @ W[128,128] + b). h fp16, W fp16, acc fp32.
// Block: 256 threads = 8 warps; warp w owns rows [blk*128 + w*16, +16).
// A loaded directly from global. Epilogue via per-warp 16x128 region of a
// 64 KB block smem buffer, single bulk store_matrix pass.
// accum_mean: accumulate column sums instead of writing output.
__global__ void k_gemm_wmma(const __half* __restrict__ hin,
                            const __half* __restrict__ Wh,
                            const float* __restrict__ bias,
                            uint2* __restrict__ hout,
                            const float* __restrict__ postscale,
                            int accum_mean, int n) {
    extern __shared__ char smem_raw[];
    __half* sW   = (__half*)smem_raw;                  // 32 KB
    float*  sOut = (float*)(smem_raw + D * D * 2);     // 8 * 16*128 fp32 = 64 KB
    float*  sSum = (float*)(smem_raw + D * D * 2 + 8 * 16 * D * 4);  // 128 f32

    int t    = threadIdx.x;
    int wid  = t >> 5;
    int lane = t & 31;

    // stage W into smem
    {
        const uint2* Wv = (const uint2*)Wh;
        uint2* sWv = (uint2*)sW;
        for (int i = t; i < D * D / 4; i += 256)
            sWv[i] = Wv[i];
    }
    if (accum_mean && t < D) sSum[t] = 0.f;
    __syncthreads();

    int row0 = blockIdx.x * 128 + wid * 16;
    bool active = (row0 + 16) <= n;   // n % 16 == 0 -> warp tiles full or empty

    if (active) {
        wmma::fragment<wmma::accumulator, 16, 16, 16, float> acc[8];
#pragma unroll
        for (int j = 0; j < 8; j++) wmma::fill_fragment(acc[j], 0.0f);

        const __half* Abase = hin + (size_t)row0 * D;
#pragma unroll
        for (int k = 0; k < 8; k++) {
            wmma::fragment<wmma::matrix_a, 16, 16, 16, __half, wmma::row_major> a;
            wmma::load_matrix_sync(a, Abase + k * 16, D);
#pragma unroll
            for (int j = 0; j < 8; j++) {
                wmma::fragment<wmma::matrix_b, 16, 16, 16, __half, wmma::row_major> b;
                wmma::load_matrix_sync(b, sW + k * 16 * D + j * 16, D);
                wmma::mma_sync(acc[j], a, b, acc[j]);
            }
        }

        // bulk dump to this warp's private 16x128 smem tile
        float* myOut = sOut + wid * 16 * D;
#pragma unroll
        for (int j = 0; j < 8; j++)
            wmma::store_matrix_sync(myOut + j * 16, acc[j], D, wmma::mem_row_major);
        __syncwarp();

        // epilogue: lane handles cols [lane*4, lane*4+4) over 16 rows
        float4 bj = *(const float4*)&bias[lane * 4];
        float cs0 = 0.f, cs1 = 0.f, cs2 = 0.f, cs3 = 0.f;
#pragma unroll
        for (int r = 0; r < 16; r++) {
            int row = row0 + r;
            float4 v = *(float4*)&myOut[r * D + lane * 4];
            v.x = fmaxf(v.x + bj.x, 0.f);
            v.y = fmaxf(v.y + bj.y, 0.f);
            v.z = fmaxf(v.z + bj.z, 0.f);
            v.w = fmaxf(v.w + bj.w, 0.f);
            if (accum_mean) {
                cs0 += v.x; cs1 += v.y; cs2 += v.z; cs3 += v.w;
            } else {
                float ps = postscale ? postscale[row] : 1.0f;
                __half2 o0 = __floats2half2_rn(ps * v.x, ps * v.y);
                __half2 o1 = __floats2half2_rn(ps * v.z, ps * v.w);
                uint2 o;
                o.x = *(unsigned*)&o0;
                o.y = *(unsigned*)&o1;
                hout[(size_t)row * 32 + lane] = o;
            }
        }
        if (accum_mean) {
            int cb = lane * 4;
            atomicAdd(&sSum[cb + 0], cs0);
            atomicAdd(&sSum[cb + 1], cs1);
            atomicAdd(&sSum[cb + 2], cs2);
            atomicAdd(&sSum[cb + 3], cs3);
        }
    }

    if (accum_mean) {
        __syncthreads();
        if (t < D) atomicAdd(&g_accum[t], sSum[t]);
    }
}

// ---------------- head: relu(hg@Wf1+bf1) -> relu(@Wf2+bf2) -> sigmoid ------
__global__ void k_head(const float* __restrict__ Wf1, const float* __restrict__ bf1,
                       const float* __restrict__ Wf2, const float* __restrict__ bf2,
                       float* __restrict__ out, float inv_n) {
    __shared__ float hg[D];
    __shared__ float red[D];
    int j = threadIdx.x;  // 128 threads
    hg[j] = g_accum[j] * inv_n;
    __syncthreads();
    float a = bf1[j];
#pragma unroll 4
    for (int k = 0; k < D; k++)
        a = fmaf(hg[k], Wf1[k * D + j], a);
    a = fmaxf(a, 0.f);
    red[j] = a * Wf2[j];
    __syncthreads();
    for (int off = 64; off > 0; off >>= 1) {
        if (j < off) red[j] += red[j + off];
        __syncthreads();
    }
    if (j == 0) {
        float o = fmaxf(red[0] + bf2[0], 0.f);
        out[0] = 1.f / (1.f + expf(-o));
    }
}

// ---------------- launch ----------------------------------------------------
extern "C" void kernel_launch(void* const* d_in, const int* in_sizes, int n_in,
                              void* d_out, int out_size) {
    const float* x   = (const float*)d_in[0];
    const int*   src = (const int*)d_in[1];
    const int*   dst = (const int*)d_in[2];
    const float* W1  = (const float*)d_in[3];
    const float* b1  = (const float*)d_in[4];
    const float* W2  = (const float*)d_in[5];
    const float* b2  = (const float*)d_in[6];
    const float* Wf1 = (const float*)d_in[7];
    const float* bf1 = (const float*)d_in[8];
    const float* Wf2 = (const float*)d_in[9];
    const float* bf2 = (const float*)d_in[10];
    float* out = (float*)d_out;

    int n = in_sizes[0] / D;   // nodes
    int e = in_sizes[1];       // edges

    uint4 *hX = nullptr, *hA = nullptr, *hB = nullptr;
    uint2 *W1h = nullptr, *W2h = nullptr;
    float *nrm = nullptr, *nrm2 = nullptr;
    cudaGetSymbolAddress((void**)&hX,   g_hX);
    cudaGetSymbolAddress((void**)&hA,   g_hA);
    cudaGetSymbolAddress((void**)&hB,   g_hB);
    cudaGetSymbolAddress((void**)&W1h,  g_W1h);
    cudaGetSymbolAddress((void**)&W2h,  g_W2h);
    cudaGetSymbolAddress((void**)&nrm,  g_norm);
    cudaGetSymbolAddress((void**)&nrm2, g_norm2);

    const int smem_gemm = D * D * 2 + 8 * 16 * D * 4 + 512;  // 32+64 KB + sums
    cudaFuncSetAttribute(k_gemm_wmma, cudaFuncAttributeMaxDynamicSharedMemorySize, smem_gemm);

    int gb_n = (n + 255) / 256;
    int gb_p = (n + 7) / 8;          // 8 warps (nodes) per 256-thread block
    int gb_g = (n + 127) / 128;      // 128 rows per GEMM block
    int nb   = (n + 1023) / 1024;    // scan blocks
    int t4   = n * 32;               // float4 count of x
    int e4   = e / 4;

    // ---- CSR build + norms ----
    k_init<<<gb_n, 256>>>(n);
    k_deg<<<(e4 + 255) / 256, 256>>>((const int4*)dst, e4);
    if (e4 * 4 < e) k_deg_tail<<<1, 256>>>(dst, e4 * 4, e);
    k_scan1<<<nb, 1024>>>(n);
    k_scan2<<<1, 1024>>>(nb);
    k_scan3<<<gb_n, 256>>>(n, e);
    k_fill<<<(e4 + 255) / 256, 256>>>((const int4*)src, (const int4*)dst, e4);
    if (e4 * 4 < e) k_fill_tail<<<1, 256>>>(src, dst, e4 * 4, e);

    // ---- convert weights + prescale x to fp16 ----
    k_cvtW<<<(D * D / 4 + 255) / 256, 256>>>((const float4*)W1, W1h, D * D / 4);
    k_cvtW<<<(D * D / 4 + 255) / 256, 256>>>((const float4*)W2, W2h, D * D / 4);
    k_prescale<<<(t4 + 255) / 256, 256>>>((const float4*)x, (uint2*)hX, t4);

    // ---- chain 1: P^3 (pure adds; norm factors folded) ----
    k_prop_add<<<gb_p, 256>>>(hX, hA, nrm2, n);   // out *= norm^2
    k_prop_add<<<gb_p, 256>>>(hA, hB, nrm2, n);   // out *= norm^2
    k_prop_add<<<gb_p, 256>>>(hB, hA, nrm, n);    // out *= norm (true h)

    // ---- relu(h @ W1 + b1), postscale norm, write fp16 ----
    k_gemm_wmma<<<gb_g, 256, smem_gemm>>>((const __half*)hA, (const __half*)W1h,
                                          b1, (uint2*)hB, nrm, 0, n);

    // ---- chain 2: P^3 (pure adds) ----
    k_prop_add<<<gb_p, 256>>>(hB, hA, nrm2, n);
    k_prop_add<<<gb_p, 256>>>(hA, hB, nrm2, n);
    k_prop_add<<<gb_p, 256>>>(hB, hA, nrm, n);

    // ---- relu(h @ W2 + b2) with fused column-mean (no h write) ----
    k_gemm_wmma<<<gb_g, 256, smem_gemm>>>((const __half*)hA, (const __half*)W2h,
                                          b2, nullptr, nullptr, 1, n);

    // ---- head ----
    k_head<<<1, D>>>(Wf1, bf1, Wf2, bf2, out, 1.0f / (float)n);
}

// round 16
// speedup vs baseline: 1.3868x; 1.3868x over previous
#include <cuda_runtime.h>
#include <cuda_fp16.h>
#include <mma.h>
#include <math.h>

using namespace nvcuda;

#define NMAX 100000
#define EMAX 3200000
#define D 128

// ---------------- scratch (device globals: allocation-guard-safe) ----------
__device__ int   g_deg[NMAX];
__device__ int   g_cursor[NMAX];
__device__ int   g_rowstart[NMAX + 1];
__device__ int   g_part[1024];
__device__ float g_norm[NMAX];    // deg^-1/2
__device__ float g_norm2[NMAX];   // deg^-1
__device__ __align__(16) int g_csr_src[EMAX];
// fp16 feature rows: 128 halfs = 256 B = 32 uint2 per row
__device__ __align__(16) uint2 g_hX[(size_t)NMAX * 32];
__device__ __align__(16) uint2 g_hA[(size_t)NMAX * 32];
__device__ __align__(16) uint2 g_hB[(size_t)NMAX * 32];
__device__ __align__(16) __half g_W1h[D * D];
__device__ __align__(16) __half g_W2h[D * D];
__device__ float g_accum[D];

// ---------------- init: zero degree counters + mean accumulator ------------
__global__ void k_init(int n) {
    int i = blockIdx.x * blockDim.x + threadIdx.x;
    if (i < n) g_deg[i] = 0;
    if (i < D) g_accum[i] = 0.f;
}

// ---------------- degree count (int4 vectorized) ---------------------------
__global__ void k_deg(const int4* __restrict__ dst4, int e4) {
    int i = blockIdx.x * blockDim.x + threadIdx.x;
    if (i < e4) {
        int4 d = dst4[i];
        atomicAdd(&g_deg[d.x], 1);
        atomicAdd(&g_deg[d.y], 1);
        atomicAdd(&g_deg[d.z], 1);
        atomicAdd(&g_deg[d.w], 1);
    }
}
__global__ void k_deg_tail(const int* __restrict__ dst, int beg, int e_cnt) {
    int i = beg + blockIdx.x * blockDim.x + threadIdx.x;
    if (i < e_cnt) atomicAdd(&g_deg[dst[i]], 1);
}

// ---------------- scan phase 1: local exclusive scan + totals + norms ------
__global__ void k_scan1(int n) {
    __shared__ int s[1024];
    int t = threadIdx.x;
    int i = blockIdx.x * 1024 + t;
    int v = (i < n) ? g_deg[i] : 0;
    s[t] = v;
    __syncthreads();
    for (int off = 1; off < 1024; off <<= 1) {
        int tmp = (t >= off) ? s[t - off] : 0;
        __syncthreads();
        s[t] += tmp;
        __syncthreads();
    }
    if (i < n) {
        g_rowstart[i] = s[t] - v;          // local exclusive
        float d = (float)v;
        if (d < 1.f) d = 1.f;
        float nr = rsqrtf(d);
        g_norm[i]  = nr;
        g_norm2[i] = nr * nr;
    }
    if (t == 1023) g_part[blockIdx.x] = s[t];
}

// ---------------- scan phase 3: self-computed prefix + offsets + cursor ----
// Block b covers nodes [b*256, b*256+256), all inside scan1 block (b>>2).
// Needed prefix = sum of g_part[j] for j < (b>>2) (<= 98 values).
__global__ void k_scan3(int n, int e_cnt) {
    __shared__ int sint[256];
    int b = blockIdx.x;
    int t = threadIdx.x;
    int lim = b >> 2;
    sint[t] = (t < lim) ? g_part[t] : 0;
    __syncthreads();
    for (int off = 128; off > 0; off >>= 1) {
        if (t < off) sint[t] += sint[t + off];
        __syncthreads();
    }
    int pref = sint[0];
    int i = b * 256 + t;
    if (i < n) {
        int r = g_rowstart[i] + pref;
        g_rowstart[i] = r;
        g_cursor[i]   = r;
    }
    if (b == 0 && t == 0) g_rowstart[n] = e_cnt;
}

// ---------------- CSR fill (int4 vectorized) -------------------------------
__global__ void k_fill(const int4* __restrict__ src4, const int4* __restrict__ dst4, int e4) {
    int i = blockIdx.x * blockDim.x + threadIdx.x;
    if (i < e4) {
        int4 s = src4[i];
        int4 d = dst4[i];
        int p;
        p = atomicAdd(&g_cursor[d.x], 1); g_csr_src[p] = s.x;
        p = atomicAdd(&g_cursor[d.y], 1); g_csr_src[p] = s.y;
        p = atomicAdd(&g_cursor[d.z], 1); g_csr_src[p] = s.z;
        p = atomicAdd(&g_cursor[d.w], 1); g_csr_src[p] = s.w;
    }
}
__global__ void k_fill_tail(const int* __restrict__ src, const int* __restrict__ dst,
                            int beg, int e_cnt) {
    int i = beg + blockIdx.x * blockDim.x + threadIdx.x;
    if (i < e_cnt) {
        int d = dst[i];
        int pos = atomicAdd(&g_cursor[d], 1);
        g_csr_src[pos] = src[i];
    }
}

// ---------------- weight fp32 -> fp16 --------------------------------------
__global__ void k_cvtW(const float4* __restrict__ W, uint2* __restrict__ Wh, int total4) {
    int i = blockIdx.x * blockDim.x + threadIdx.x;
    if (i < total4) {
        float4 v = W[i];
        __half2 a = __floats2half2_rn(v.x, v.y);
        __half2 b = __floats2half2_rn(v.z, v.w);
        uint2 o;
        o.x = *(unsigned*)&a;
        o.y = *(unsigned*)&b;
        Wh[i] = o;
    }
}

// ---------------- prescale: xs = fp16(norm[row] * x) -----------------------
__global__ void k_prescale(const float4* __restrict__ x, uint2* __restrict__ xs, int total4) {
    int i = blockIdx.x * blockDim.x + threadIdx.x;
    if (i < total4) {
        float nr = g_norm[i >> 5];
        float4 v = x[i];
        __half2 a = __floats2half2_rn(nr * v.x, nr * v.y);
        __half2 b = __floats2half2_rn(nr * v.z, nr * v.w);
        uint2 o;
        o.x = *(unsigned*)&a;
        o.y = *(unsigned*)&b;
        xs[i] = o;
    }
}

// ---------------- pure-add fp16 propagation (R9/R14-proven, full warp) -----
// out[w] = fp16( scl[w] * sum_e in[src_e] ) ; rows are 32 uint2 (128 halfs)
__global__ void k_prop_add(const uint2* __restrict__ hin, uint2* __restrict__ hout,
                           const float* __restrict__ scl, int n) {
    int w    = (int)((blockIdx.x * (unsigned)blockDim.x + threadIdx.x) >> 5);
    int lane = threadIdx.x & 31;
    if (w >= n) return;
    int e   = g_rowstart[w];
    int end = g_rowstart[w + 1];

    __half2 z = __float2half2_rn(0.f);
    __half2 a0x = z, a0y = z, a1x = z, a1y = z;

    for (; e + 4 <= end; e += 4) {
        int s0 = g_csr_src[e];
        int s1 = g_csr_src[e + 1];
        int s2 = g_csr_src[e + 2];
        int s3 = g_csr_src[e + 3];
        uint2 r0 = __ldg(&hin[s0 * 32 + lane]);
        uint2 r1 = __ldg(&hin[s1 * 32 + lane]);
        uint2 r2 = __ldg(&hin[s2 * 32 + lane]);
        uint2 r3 = __ldg(&hin[s3 * 32 + lane]);
        a0x = __hadd2(a0x, *(__half2*)&r0.x); a0y = __hadd2(a0y, *(__half2*)&r0.y);
        a1x = __hadd2(a1x, *(__half2*)&r1.x); a1y = __hadd2(a1y, *(__half2*)&r1.y);
        a0x = __hadd2(a0x, *(__half2*)&r2.x); a0y = __hadd2(a0y, *(__half2*)&r2.y);
        a1x = __hadd2(a1x, *(__half2*)&r3.x); a1y = __hadd2(a1y, *(__half2*)&r3.y);
    }
    for (; e < end; e++) {
        int s0 = g_csr_src[e];
        uint2 r0 = __ldg(&hin[s0 * 32 + lane]);
        a0x = __hadd2(a0x, *(__half2*)&r0.x); a0y = __hadd2(a0y, *(__half2*)&r0.y);
    }
    float f = scl[w];
    float2 sx = __half22float2(__hadd2(a0x, a1x));
    float2 sy = __half22float2(__hadd2(a0y, a1y));
    __half2 o0 = __floats2half2_rn(f * sx.x, f * sx.y);
    __half2 o1 = __floats2half2_rn(f * sy.x, f * sy.y);
    uint2 o;
    o.x = *(unsigned*)&o0;
    o.y = *(unsigned*)&o1;
    hout[w * 32 + lane] = o;
}

// ---------------- tensor-core GEMM + bias + relu (R14-proven) --------------
// C[n,128] = relu(h[n,128] @ W[128,128] + b). h fp16, W fp16, acc fp32.
// Block: 256 threads = 8 warps; warp w owns rows [blk*128 + w*16, +16).
// A loaded directly from global. Epilogue via per-warp 16x128 region of a
// 64 KB block smem buffer, single bulk store_matrix pass.
// accum_mean: accumulate column sums instead of writing output.
__global__ void k_gemm_wmma(const __half* __restrict__ hin,
                            const __half* __restrict__ Wh,
                            const float* __restrict__ bias,
                            uint2* __restrict__ hout,
                            const float* __restrict__ postscale,
                            int accum_mean, int n) {
    extern __shared__ char smem_raw[];
    __half* sW   = (__half*)smem_raw;                  // 32 KB
    float*  sOut = (float*)(smem_raw + D * D * 2);     // 8 * 16*128 fp32 = 64 KB
    float*  sSum = (float*)(smem_raw + D * D * 2 + 8 * 16 * D * 4);  // 128 f32

    int t    = threadIdx.x;
    int wid  = t >> 5;
    int lane = t & 31;

    // stage W into smem
    {
        const uint2* Wv = (const uint2*)Wh;
        uint2* sWv = (uint2*)sW;
        for (int i = t; i < D * D / 4; i += 256)
            sWv[i] = Wv[i];
    }
    if (accum_mean && t < D) sSum[t] = 0.f;
    __syncthreads();

    int row0 = blockIdx.x * 128 + wid * 16;
    bool active = (row0 + 16) <= n;   // n % 16 == 0 -> warp tiles full or empty

    if (active) {
        wmma::fragment<wmma::accumulator, 16, 16, 16, float> acc[8];
#pragma unroll
        for (int j = 0; j < 8; j++) wmma::fill_fragment(acc[j], 0.0f);

        const __half* Abase = hin + (size_t)row0 * D;
#pragma unroll
        for (int k = 0; k < 8; k++) {
            wmma::fragment<wmma::matrix_a, 16, 16, 16, __half, wmma::row_major> a;
            wmma::load_matrix_sync(a, Abase + k * 16, D);
#pragma unroll
            for (int j = 0; j < 8; j++) {
                wmma::fragment<wmma::matrix_b, 16, 16, 16, __half, wmma::row_major> b;
                wmma::load_matrix_sync(b, sW + k * 16 * D + j * 16, D);
                wmma::mma_sync(acc[j], a, b, acc[j]);
            }
        }

        // bulk dump to this warp's private 16x128 smem tile
        float* myOut = sOut + wid * 16 * D;
#pragma unroll
        for (int j = 0; j < 8; j++)
            wmma::store_matrix_sync(myOut + j * 16, acc[j], D, wmma::mem_row_major);
        __syncwarp();

        // epilogue: lane handles cols [lane*4, lane*4+4) over 16 rows
        float4 bj = *(const float4*)&bias[lane * 4];
        float cs0 = 0.f, cs1 = 0.f, cs2 = 0.f, cs3 = 0.f;
#pragma unroll
        for (int r = 0; r < 16; r++) {
            int row = row0 + r;
            float4 v = *(float4*)&myOut[r * D + lane * 4];
            v.x = fmaxf(v.x + bj.x, 0.f);
            v.y = fmaxf(v.y + bj.y, 0.f);
            v.z = fmaxf(v.z + bj.z, 0.f);
            v.w = fmaxf(v.w + bj.w, 0.f);
            if (accum_mean) {
                cs0 += v.x; cs1 += v.y; cs2 += v.z; cs3 += v.w;
            } else {
                float ps = postscale ? postscale[row] : 1.0f;
                __half2 o0 = __floats2half2_rn(ps * v.x, ps * v.y);
                __half2 o1 = __floats2half2_rn(ps * v.z, ps * v.w);
                uint2 o;
                o.x = *(unsigned*)&o0;
                o.y = *(unsigned*)&o1;
                hout[(size_t)row * 32 + lane] = o;
            }
        }
        if (accum_mean) {
            int cb = lane * 4;
            atomicAdd(&sSum[cb + 0], cs0);
            atomicAdd(&sSum[cb + 1], cs1);
            atomicAdd(&sSum[cb + 2], cs2);
            atomicAdd(&sSum[cb + 3], cs3);
        }
    }

    if (accum_mean) {
        __syncthreads();
        if (t < D) atomicAdd(&g_accum[t], sSum[t]);
    }
}

// ---------------- head: relu(hg@Wf1+bf1) -> relu(@Wf2+bf2) -> sigmoid ------
__global__ void k_head(const float* __restrict__ Wf1, const float* __restrict__ bf1,
                       const float* __restrict__ Wf2, const float* __restrict__ bf2,
                       float* __restrict__ out, float inv_n) {
    __shared__ float hg[D];
    __shared__ float red[D];
    int j = threadIdx.x;  // 128 threads
    hg[j] = g_accum[j] * inv_n;
    __syncthreads();
    float a = bf1[j];
#pragma unroll 4
    for (int k = 0; k < D; k++)
        a = fmaf(hg[k], Wf1[k * D + j], a);
    a = fmaxf(a, 0.f);
    red[j] = a * Wf2[j];
    __syncthreads();
    for (int off = 64; off > 0; off >>= 1) {
        if (j < off) red[j] += red[j + off];
        __syncthreads();
    }
    if (j == 0) {
        float o = fmaxf(red[0] + bf2[0], 0.f);
        out[0] = 1.f / (1.f + expf(-o));
    }
}

// ---------------- launch ----------------------------------------------------
extern "C" void kernel_launch(void* const* d_in, const int* in_sizes, int n_in,
                              void* d_out, int out_size) {
    const float* x   = (const float*)d_in[0];
    const int*   src = (const int*)d_in[1];
    const int*   dst = (const int*)d_in[2];
    const float* W1  = (const float*)d_in[3];
    const float* b1  = (const float*)d_in[4];
    const float* W2  = (const float*)d_in[5];
    const float* b2  = (const float*)d_in[6];
    const float* Wf1 = (const float*)d_in[7];
    const float* bf1 = (const float*)d_in[8];
    const float* Wf2 = (const float*)d_in[9];
    const float* bf2 = (const float*)d_in[10];
    float* out = (float*)d_out;

    int n = in_sizes[0] / D;   // nodes
    int e = in_sizes[1];       // edges

    uint2 *hX = nullptr, *hA = nullptr, *hB = nullptr;
    uint2 *W1h = nullptr, *W2h = nullptr;
    float *nrm = nullptr, *nrm2 = nullptr;
    cudaGetSymbolAddress((void**)&hX,   g_hX);
    cudaGetSymbolAddress((void**)&hA,   g_hA);
    cudaGetSymbolAddress((void**)&hB,   g_hB);
    cudaGetSymbolAddress((void**)&W1h,  g_W1h);
    cudaGetSymbolAddress((void**)&W2h,  g_W2h);
    cudaGetSymbolAddress((void**)&nrm,  g_norm);
    cudaGetSymbolAddress((void**)&nrm2, g_norm2);

    const int smem_gemm = D * D * 2 + 8 * 16 * D * 4 + 512;  // 32+64 KB + sums
    cudaFuncSetAttribute(k_gemm_wmma, cudaFuncAttributeMaxDynamicSharedMemorySize, smem_gemm);

    // side streams + events (created once; event fork/join is graph-capturable)
    static cudaStream_t sPS = nullptr, sW = nullptr;
    static cudaEvent_t evRoot = nullptr, evNorm = nullptr, evPS = nullptr, evW = nullptr;
    if (!sPS) {
        cudaStreamCreateWithFlags(&sPS, cudaStreamNonBlocking);
        cudaStreamCreateWithFlags(&sW,  cudaStreamNonBlocking);
        cudaEventCreateWithFlags(&evRoot, cudaEventDisableTiming);
        cudaEventCreateWithFlags(&evNorm, cudaEventDisableTiming);
        cudaEventCreateWithFlags(&evPS,   cudaEventDisableTiming);
        cudaEventCreateWithFlags(&evW,    cudaEventDisableTiming);
    }

    int gb_n = (n + 255) / 256;
    int gb_p = (n + 7) / 8;          // 8 warps (nodes) per 256-thread block
    int gb_g = (n + 127) / 128;      // 128 rows per GEMM block
    int nb   = (n + 1023) / 1024;    // scan blocks
    int t4   = n * 32;               // float4 count of x
    int e4   = e / 4;

    // ---- fork: weight conversion on side stream (no dependencies) ----
    cudaEventRecord(evRoot, 0);
    cudaStreamWaitEvent(sW, evRoot, 0);
    k_cvtW<<<(D * D / 4 + 255) / 256, 256, 0, sW>>>((const float4*)W1, W1h, D * D / 4);
    k_cvtW<<<(D * D / 4 + 255) / 256, 256, 0, sW>>>((const float4*)W2, W2h, D * D / 4);
    cudaEventRecord(evW, sW);

    // ---- CSR build + norms (main stream) ----
    k_init<<<gb_n, 256>>>(n);
    k_deg<<<(e4 + 255) / 256, 256>>>((const int4*)dst, e4);
    if (e4 * 4 < e) k_deg_tail<<<1, 256>>>(dst, e4 * 4, e);
    k_scan1<<<nb, 1024>>>(n);                       // norms ready here

    // ---- fork: prescale x (needs only norm) overlapped with scan3+fill ----
    cudaEventRecord(evNorm, 0);
    cudaStreamWaitEvent(sPS, evNorm, 0);
    k_prescale<<<(t4 + 255) / 256, 256, 0, sPS>>>((const float4*)x, hX, t4);
    cudaEventRecord(evPS, sPS);

    k_scan3<<<gb_n, 256>>>(n, e);
    k_fill<<<(e4 + 255) / 256, 256>>>((const int4*)src, (const int4*)dst, e4);
    if (e4 * 4 < e) k_fill_tail<<<1, 256>>>(src, dst, e4 * 4, e);

    // ---- join prescale, then chain 1: P^3 (pure adds; norm folded) ----
    cudaStreamWaitEvent(0, evPS, 0);
    k_prop_add<<<gb_p, 256>>>(hX, hA, nrm2, n);   // out *= norm^2
    k_prop_add<<<gb_p, 256>>>(hA, hB, nrm2, n);   // out *= norm^2
    k_prop_add<<<gb_p, 256>>>(hB, hA, nrm, n);    // out *= norm (true h)

    // ---- join weights, relu(h @ W1 + b1), postscale norm, write fp16 ----
    cudaStreamWaitEvent(0, evW, 0);
    k_gemm_wmma<<<gb_g, 256, smem_gemm>>>((const __half*)hA, (const __half*)W1h,
                                          b1, hB, nrm, 0, n);

    // ---- chain 2: P^3 (pure adds) ----
    k_prop_add<<<gb_p, 256>>>(hB, hA, nrm2, n);
    k_prop_add<<<gb_p, 256>>>(hA, hB, nrm2, n);
    k_prop_add<<<gb_p, 256>>>(hB, hA, nrm, n);

    // ---- relu(h @ W2 + b2) with fused column-mean (no h write) ----
    k_gemm_wmma<<<gb_g, 256, smem_gemm>>>((const __half*)hA, (const __half*)W2h,
                                          b2, nullptr, nullptr, 1, n);

    // ---- head ----
    k_head<<<1, D>>>(Wf1, bf1, Wf2, bf2, out, 1.0f / (float)n);
}